// round 1
// baseline (speedup 1.0000x reference)
#include <cuda_runtime.h>
#include <math.h>

// ---------------- problem constants ----------------
#define Bc   4
#define Lc   2048
#define Dc   1024
#define Hc   4
#define HDc  256
#define NLc  2
#define FFc  4096
#define Mc   (Bc*Lc)     // 8192 tokens
#define D3c  (3*Dc)      // 3072

// ---------------- device scratch (static; no allocations) ----------------
__device__ float g_h  [(size_t)Mc*Dc];          // residual stream   32MB
__device__ float g_hn [(size_t)Mc*Dc];          // layernorm output  32MB
__device__ float g_qkv[(size_t)Mc*D3c];         // qkv               96MB
__device__ float g_sc [(size_t)Bc*Hc*Lc*Lc];    // attn scores      268MB
__device__ float g_o  [(size_t)Mc*Dc];          // attn output       32MB
__device__ float g_f  [(size_t)Mc*FFc];         // ff hidden        128MB

// ---------------- helpers ----------------
__device__ __forceinline__ float gelu_exact(float x) {
    return 0.5f * x * (1.0f + erff(x * 0.70710678118654752440f));
}

// ---------------- generic tiled GEMM ----------------
// C[M,N] = act( scale * A @ op(B) + bias + resid )
//   BNN = false : C += A[M,K] * B[N,K]^T   (both K-major, "NT")
//   BNN = true  : C += A[M,K] * B[K,N]     (B N-major,   "NN")
// Batched over blockIdx.z with split (outer, inner) strides: z = zo*zinner + zi.
// All dims must be multiples: M%128==0, N%128==0, K%8==0 (holds for every call here).
#define BM 128
#define BN 128
#define BK 8

template<bool BNN, int ACT, bool HB, bool HR>
__global__ __launch_bounds__(256)
void gemm_kernel(const float* __restrict__ A, int lda,
                 const float* __restrict__ B, int ldb,
                 const float* __restrict__ bias,
                 const float* __restrict__ resid,
                 float* __restrict__ C, int ldc,
                 int K, float scale,
                 long aso, long asi, long bso, long bsi, long cso, long csi,
                 int zinner)
{
    const int z  = blockIdx.z;
    const int zo = z / zinner;
    const int zi = z - zo * zinner;
    A += (size_t)zo * aso + (size_t)zi * asi;
    B += (size_t)zo * bso + (size_t)zi * bsi;
    C += (size_t)zo * cso + (size_t)zi * csi;
    const float* R = resid;  // only used non-batched (zo=zi=0 offsets)

    __shared__ float As[BK][BM];
    __shared__ float Bs[BK][BN];

    const int tid  = threadIdx.x;            // 256 threads
    const int row0 = blockIdx.y * BM;
    const int col0 = blockIdx.x * BN;

    // A (and NT-B) loader indices: 128 rows x 8 cols, one float4 per thread
    const int lrow = tid >> 1;                // 0..127
    const int lcol = (tid & 1) << 2;          // 0 or 4
    // NN-B loader indices: 8 rows x 128 cols
    const int nrow = tid >> 5;                // 0..7
    const int ncol = (tid & 31) << 2;         // 0..124

    const int tx = tid & 15;                  // 16 x 16 thread grid
    const int ty = tid >> 4;

    const float* Ap = A + (size_t)(row0 + lrow) * lda + lcol;
    const float* Bp;
    if (!BNN) Bp = B + (size_t)(col0 + lrow) * ldb + lcol;
    else      Bp = B + (size_t)nrow * ldb + col0 + ncol;

    float acc[8][8];
    #pragma unroll
    for (int i = 0; i < 8; i++)
        #pragma unroll
        for (int j = 0; j < 8; j++) acc[i][j] = 0.0f;

    for (int k0 = 0; k0 < K; k0 += BK) {
        float4 av = *(const float4*)(Ap + k0);
        As[lcol+0][lrow] = av.x;
        As[lcol+1][lrow] = av.y;
        As[lcol+2][lrow] = av.z;
        As[lcol+3][lrow] = av.w;
        if (!BNN) {
            float4 bv = *(const float4*)(Bp + k0);
            Bs[lcol+0][lrow] = bv.x;
            Bs[lcol+1][lrow] = bv.y;
            Bs[lcol+2][lrow] = bv.z;
            Bs[lcol+3][lrow] = bv.w;
        } else {
            float4 bv = *(const float4*)(Bp + (size_t)k0 * ldb);
            *(float4*)&Bs[nrow][ncol] = bv;
        }
        __syncthreads();

        #pragma unroll
        for (int kk = 0; kk < BK; kk++) {
            float ar[8], br[8];
            *(float4*)&ar[0] = *(const float4*)&As[kk][ty*8];
            *(float4*)&ar[4] = *(const float4*)&As[kk][ty*8+4];
            *(float4*)&br[0] = *(const float4*)&Bs[kk][tx*8];
            *(float4*)&br[4] = *(const float4*)&Bs[kk][tx*8+4];
            #pragma unroll
            for (int i = 0; i < 8; i++)
                #pragma unroll
                for (int j = 0; j < 8; j++)
                    acc[i][j] = fmaf(ar[i], br[j], acc[i][j]);
        }
        __syncthreads();
    }

    // epilogue
    float bcol[8];
    if (HB) {
        *(float4*)&bcol[0] = *(const float4*)&bias[col0 + tx*8];
        *(float4*)&bcol[4] = *(const float4*)&bias[col0 + tx*8 + 4];
    }
    #pragma unroll
    for (int i = 0; i < 8; i++) {
        const int r = row0 + ty*8 + i;
        const int c = col0 + tx*8;
        float v[8];
        #pragma unroll
        for (int j = 0; j < 8; j++) {
            v[j] = acc[i][j] * scale;
            if (HB) v[j] += bcol[j];
        }
        if (HR) {
            float rr[8];
            *(float4*)&rr[0] = *(const float4*)&R[(size_t)r*ldc + c];
            *(float4*)&rr[4] = *(const float4*)&R[(size_t)r*ldc + c + 4];
            #pragma unroll
            for (int j = 0; j < 8; j++) v[j] += rr[j];
        }
        if (ACT == 1) {
            #pragma unroll
            for (int j = 0; j < 8; j++) v[j] = gelu_exact(v[j]);
        }
        *(float4*)&C[(size_t)r*ldc + c]     = *(float4*)&v[0];
        *(float4*)&C[(size_t)r*ldc + c + 4] = *(float4*)&v[4];
    }
}

// ---------------- layernorm: one block per row (D=1024, 256 thr x 4 elems) ----------------
__global__ __launch_bounds__(256)
void layernorm_kernel(const float* __restrict__ x,
                      const float* __restrict__ g,
                      const float* __restrict__ b,
                      float* __restrict__ out)
{
    const int row = blockIdx.x;
    const int t   = threadIdx.x;
    const float4 v = ((const float4*)(x + (size_t)row * Dc))[t];

    float s1 = v.x + v.y + v.z + v.w;
    float s2 = v.x*v.x + v.y*v.y + v.z*v.z + v.w*v.w;

    __shared__ float sh1[8], sh2[8];
    #pragma unroll
    for (int o = 16; o > 0; o >>= 1) {
        s1 += __shfl_down_sync(0xffffffffu, s1, o);
        s2 += __shfl_down_sync(0xffffffffu, s2, o);
    }
    if ((t & 31) == 0) { sh1[t >> 5] = s1; sh2[t >> 5] = s2; }
    __syncthreads();
    if (t < 8) {
        s1 = sh1[t]; s2 = sh2[t];
        #pragma unroll
        for (int o = 4; o > 0; o >>= 1) {
            s1 += __shfl_down_sync(0xffu, s1, o);
            s2 += __shfl_down_sync(0xffu, s2, o);
        }
        if (t == 0) { sh1[0] = s1; sh2[0] = s2; }
    }
    __syncthreads();

    const float mean = sh1[0] * (1.0f / Dc);
    const float var  = sh2[0] * (1.0f / Dc) - mean * mean;
    const float rstd = rsqrtf(var + 1e-5f);

    const float4 gv = ((const float4*)g)[t];
    const float4 bv = ((const float4*)b)[t];
    float4 r;
    r.x = (v.x - mean) * rstd * gv.x + bv.x;
    r.y = (v.y - mean) * rstd * gv.y + bv.y;
    r.z = (v.z - mean) * rstd * gv.z + bv.z;
    r.w = (v.w - mean) * rstd * gv.w + bv.w;
    ((float4*)(out + (size_t)row * Dc))[t] = r;
}

// ---------------- softmax: one block per row of length L=2048 ----------------
__global__ __launch_bounds__(256)
void softmax_kernel(float* __restrict__ s)
{
    const size_t row = blockIdx.x;
    float4* p = (float4*)(s + row * (size_t)Lc);
    const int t = threadIdx.x;

    float4 a = p[t];
    float4 c = p[t + 256];

    float mx = fmaxf(fmaxf(fmaxf(a.x, a.y), fmaxf(a.z, a.w)),
                     fmaxf(fmaxf(c.x, c.y), fmaxf(c.z, c.w)));

    __shared__ float sh[8];
    #pragma unroll
    for (int o = 16; o > 0; o >>= 1) mx = fmaxf(mx, __shfl_down_sync(0xffffffffu, mx, o));
    if ((t & 31) == 0) sh[t >> 5] = mx;
    __syncthreads();
    if (t < 8) {
        mx = sh[t];
        #pragma unroll
        for (int o = 4; o > 0; o >>= 1) mx = fmaxf(mx, __shfl_down_sync(0xffu, mx, o));
        if (t == 0) sh[0] = mx;
    }
    __syncthreads();
    mx = sh[0];
    __syncthreads();

    a.x = expf(a.x - mx); a.y = expf(a.y - mx); a.z = expf(a.z - mx); a.w = expf(a.w - mx);
    c.x = expf(c.x - mx); c.y = expf(c.y - mx); c.z = expf(c.z - mx); c.w = expf(c.w - mx);

    float sm = a.x + a.y + a.z + a.w + c.x + c.y + c.z + c.w;
    #pragma unroll
    for (int o = 16; o > 0; o >>= 1) sm += __shfl_down_sync(0xffffffffu, sm, o);
    if ((t & 31) == 0) sh[t >> 5] = sm;
    __syncthreads();
    if (t < 8) {
        sm = sh[t];
        #pragma unroll
        for (int o = 4; o > 0; o >>= 1) sm += __shfl_down_sync(0xffu, sm, o);
        if (t == 0) sh[0] = sm;
    }
    __syncthreads();
    const float inv = 1.0f / sh[0];

    a.x *= inv; a.y *= inv; a.z *= inv; a.w *= inv;
    c.x *= inv; c.y *= inv; c.z *= inv; c.w *= inv;
    p[t]       = a;
    p[t + 256] = c;
}

// ---------------- host side ----------------
extern "C" void kernel_launch(void* const* d_in, const int* in_sizes, int n_in,
                              void* d_out, int out_size)
{
    const float* x    = (const float*)d_in[0];
    const float* w3d  = (const float*)d_in[1];
    const float* b3d  = (const float*)d_in[2];
    const float* ln1g = (const float*)d_in[3];
    const float* ln1b = (const float*)d_in[4];
    const float* wqkv = (const float*)d_in[5];
    const float* bqkv = (const float*)d_in[6];
    const float* wprj = (const float*)d_in[7];
    const float* bprj = (const float*)d_in[8];
    const float* ln2g = (const float*)d_in[9];
    const float* ln2b = (const float*)d_in[10];
    const float* w1   = (const float*)d_in[11];
    const float* b1   = (const float*)d_in[12];
    const float* w2   = (const float*)d_in[13];
    const float* b2   = (const float*)d_in[14];
    const float* lnfg = (const float*)d_in[15];
    const float* lnfb = (const float*)d_in[16];
    float* out = (float*)d_out;

    float *h, *hn, *qkv, *sc, *o, *f;
    cudaGetSymbolAddress((void**)&h,   g_h);
    cudaGetSymbolAddress((void**)&hn,  g_hn);
    cudaGetSymbolAddress((void**)&qkv, g_qkv);
    cudaGetSymbolAddress((void**)&sc,  g_sc);
    cudaGetSymbolAddress((void**)&o,   g_o);
    cudaGetSymbolAddress((void**)&f,   g_f);

    const dim3 blk(256);

    // ---- embed: h = x @ w3d^T + b3d    [8192,1024] ----
    gemm_kernel<false,0,true,false><<<dim3(Dc/BN, Mc/BM, 1), blk>>>(
        x, D3c, w3d, D3c, b3d, nullptr, h, Dc, D3c, 1.0f,
        0,0,0,0,0,0, 1);

    for (int i = 0; i < NLc; i++) {
        // ---- ln1 ----
        layernorm_kernel<<<Mc, blk>>>(h, ln1g + (size_t)i*Dc, ln1b + (size_t)i*Dc, hn);

        // ---- qkv = hn @ wqkv^T + bqkv   [8192,3072] ----
        gemm_kernel<false,0,true,false><<<dim3(D3c/BN, Mc/BM, 1), blk>>>(
            hn, Dc, wqkv + (size_t)i*D3c*Dc, Dc, bqkv + (size_t)i*D3c, nullptr,
            qkv, D3c, Dc, 1.0f, 0,0,0,0,0,0, 1);

        // ---- scores[b,h,q,k] = scale * Q . K   (batched NT, z = b*H + head) ----
        gemm_kernel<false,0,false,false><<<dim3(Lc/BN, Lc/BM, Bc*Hc), blk>>>(
            qkv,        D3c,            // Q base, row stride 3D
            qkv + Dc,   D3c,            // K base
            nullptr, nullptr,
            sc, Lc,
            HDc, 0.0625f,               // 1/sqrt(256)
            (long)Lc*D3c, (long)HDc,    // A: batch, head strides
            (long)Lc*D3c, (long)HDc,    // B
            (long)Hc*Lc*Lc, (long)Lc*Lc,// C
            Hc);

        // ---- softmax over k ----
        softmax_kernel<<<Bc*Hc*Lc, blk>>>(sc);

        // ---- o[b,q,h,:] = scores @ V   (batched NN) ----
        gemm_kernel<true,0,false,false><<<dim3(HDc/BN, Lc/BM, Bc*Hc), blk>>>(
            sc,         Lc,
            qkv + 2*Dc, D3c,
            nullptr, nullptr,
            o, Dc,
            Lc, 1.0f,
            (long)Hc*Lc*Lc, (long)Lc*Lc,
            (long)Lc*D3c,  (long)HDc,
            (long)Lc*Dc,   (long)HDc,
            Hc);

        // ---- h = h + o @ wproj^T + bproj ----
        gemm_kernel<false,0,true,true><<<dim3(Dc/BN, Mc/BM, 1), blk>>>(
            o, Dc, wprj + (size_t)i*Dc*Dc, Dc, bprj + (size_t)i*Dc, h,
            h, Dc, Dc, 1.0f, 0,0,0,0,0,0, 1);

        // ---- ln2 ----
        layernorm_kernel<<<Mc, blk>>>(h, ln2g + (size_t)i*Dc, ln2b + (size_t)i*Dc, hn);

        // ---- f = gelu(hn @ w1^T + b1)   [8192,4096] ----
        gemm_kernel<false,1,true,false><<<dim3(FFc/BN, Mc/BM, 1), blk>>>(
            hn, Dc, w1 + (size_t)i*FFc*Dc, Dc, b1 + (size_t)i*FFc, nullptr,
            f, FFc, Dc, 1.0f, 0,0,0,0,0,0, 1);

        // ---- h = h + f @ w2^T + b2 ----
        gemm_kernel<false,0,true,true><<<dim3(Dc/BN, Mc/BM, 1), blk>>>(
            f, FFc, w2 + (size_t)i*Dc*FFc, FFc, b2 + (size_t)i*Dc, h,
            h, Dc, FFc, 1.0f, 0,0,0,0,0,0, 1);
    }

    // ---- final layernorm -> out ----
    layernorm_kernel<<<Mc, blk>>>(h, lnfg, lnfb, out);
}

// round 3
// speedup vs baseline: 2.2531x; 2.2531x over previous
#include <cuda_runtime.h>
#include <cuda_bf16.h>
#include <math.h>
#include <stdint.h>

// ---------------- problem constants ----------------
#define Bc   4
#define Lc   2048
#define Dc   1024
#define Hc   4
#define HDc  256
#define NLc  2
#define FFc  4096
#define Mc   (Bc*Lc)     // 8192 tokens
#define D3c  (3*Dc)      // 3072

// ---------------- device scratch (static; no allocations) ----------------
__device__ float g_h  [(size_t)Mc*Dc];
__device__ float g_hn [(size_t)Mc*Dc];
__device__ float g_qkv[(size_t)Mc*D3c];
__device__ float g_sc [(size_t)Bc*Hc*Lc*Lc];
__device__ float g_o  [(size_t)Mc*Dc];
__device__ float g_f  [(size_t)Mc*FFc];
__device__ float g_vt [(size_t)Bc*Hc*HDc*Lc];   // V transposed per (b,h): [HD, L]

// ---------------- helpers ----------------
__device__ __forceinline__ uint32_t smem_u32(const void* p) {
    uint32_t a;
    asm("{ .reg .u64 t; cvta.to.shared.u64 t, %1; cvt.u32.u64 %0, t; }" : "=r"(a) : "l"(p));
    return a;
}

__device__ __forceinline__ void ldsm4(uint32_t* r, uint32_t addr) {
    asm volatile("ldmatrix.sync.aligned.m8n8.x4.shared.b16 {%0,%1,%2,%3}, [%4];"
        : "=r"(r[0]), "=r"(r[1]), "=r"(r[2]), "=r"(r[3]) : "r"(addr));
}

__device__ __forceinline__ void mma16816(float* d, const uint32_t* a, const uint32_t* b) {
    asm volatile(
        "mma.sync.aligned.m16n8k16.row.col.f32.bf16.bf16.f32 "
        "{%0,%1,%2,%3}, {%4,%5,%6,%7}, {%8,%9}, {%0,%1,%2,%3};"
        : "+f"(d[0]), "+f"(d[1]), "+f"(d[2]), "+f"(d[3])
        : "r"(a[0]), "r"(a[1]), "r"(a[2]), "r"(a[3]), "r"(b[0]), "r"(b[1]));
}

__device__ __forceinline__ float gelu_exact(float x) {
    return 0.5f * x * (1.0f + erff(x * 0.70710678118654752440f));
}

// split fp32x4 -> hi/lo bf16x4 packed as uint2
__device__ __forceinline__ void split4(float4 v, uint2& Hh, uint2& Ll) {
    __nv_bfloat16 hx = __float2bfloat16_rn(v.x);
    __nv_bfloat16 hy = __float2bfloat16_rn(v.y);
    __nv_bfloat16 hz = __float2bfloat16_rn(v.z);
    __nv_bfloat16 hw = __float2bfloat16_rn(v.w);
    union { __nv_bfloat162 b2[2]; uint2 u; } H, L;
    H.b2[0] = __halves2bfloat162(hx, hy);
    H.b2[1] = __halves2bfloat162(hz, hw);
    L.b2[0] = __halves2bfloat162(__float2bfloat16_rn(v.x - __bfloat162float(hx)),
                                 __float2bfloat16_rn(v.y - __bfloat162float(hy)));
    L.b2[1] = __halves2bfloat162(__float2bfloat16_rn(v.z - __bfloat162float(hz)),
                                 __float2bfloat16_rn(v.w - __bfloat162float(hw)));
    Hh = H.u; Ll = L.u;
}

// ---------------- tensor-core GEMM (mma.sync bf16, split-fp32) ----------------
// C[M,N] = act(scale * A[M,K] @ B[N,K]^T + bias + resid), all fp32 in gmem.
// CTA tile 128x128, K-chunk 64, 8 warps (4 row-bands x 2 col-bands), warp tile 32x64.
#define KC   64
#define SKB  72                      // smem row stride in bf16 elems (144B; conflict-free)
#define T_ELE (128*SKB)              // elems per 128x64 tile = 9216
#define AH_O 0
#define AL_O (T_ELE)
#define BH_O (2*T_ELE)
#define BL_O (3*T_ELE)
#define STAGE_E (4*T_ELE)            // 36864 elems
#define SMEM_DYN (2*STAGE_E*2)       // 147456 bytes

template<bool HB, bool HR, int ACT>
__global__ __launch_bounds__(256, 1) void tc_gemm(
    const float* __restrict__ A, int lda,
    const float* __restrict__ B, int ldb,
    const float* __restrict__ bias,
    const float* __restrict__ resid,
    float* __restrict__ C, int ldc,
    int K, float scale,
    long aso, long asi, long bso, long bsi, long cso, long csi, int zinner)
{
    const int z  = blockIdx.z;
    const int zo = z / zinner;
    const int zi = z - zo * zinner;
    A += (size_t)zo * aso + (size_t)zi * asi;
    B += (size_t)zo * bso + (size_t)zi * bsi;
    C += (size_t)zo * cso + (size_t)zi * csi;

    extern __shared__ char dsm[];
    const uint32_t sb32 = smem_u32(dsm);

    const int tid  = threadIdx.x;
    const int wid  = tid >> 5;
    const int lane = tid & 31;
    const int wr   = wid & 3;        // row band (32 rows)
    const int wc   = wid >> 2;       // col band (64 cols)
    const int row0 = blockIdx.y * 128;
    const int col0 = blockIdx.x * 128;

    const int lr0 = tid >> 4;        // loader: base row (stride 16 over 8 iters)
    const int lcg = (tid & 15) << 2; // loader: col (4 floats)

    float acc[2][8][4];
    #pragma unroll
    for (int mt = 0; mt < 2; mt++)
        #pragma unroll
        for (int nt = 0; nt < 8; nt++)
            #pragma unroll
            for (int j = 0; j < 4; j++) acc[mt][nt][j] = 0.0f;

    const int nc = K / KC;

    // ---- prologue: fill stage 0 ----
    {
        const float* Ab = A + (size_t)row0 * lda;
        const float* Bb = B + (size_t)col0 * ldb;
        #pragma unroll
        for (int it = 0; it < 8; it++) {
            int r = lr0 + it * 16;
            uint2 Hh, Ll;
            split4(*(const float4*)(Ab + (size_t)r * lda + lcg), Hh, Ll);
            *(uint2*)(dsm + (AH_O + r * SKB + lcg) * 2) = Hh;
            *(uint2*)(dsm + (AL_O + r * SKB + lcg) * 2) = Ll;
            split4(*(const float4*)(Bb + (size_t)r * ldb + lcg), Hh, Ll);
            *(uint2*)(dsm + (BH_O + r * SKB + lcg) * 2) = Hh;
            *(uint2*)(dsm + (BL_O + r * SKB + lcg) * 2) = Ll;
        }
    }
    __syncthreads();

    // fragment address offsets (lane-dependent)
    const int ro = lane & 15;
    const int co = (lane >> 4) << 3;

    for (int c = 0; c < nc; c++) {
        const int s = c & 1;
        const uint32_t sOff = sb32 + (uint32_t)s * (STAGE_E * 2);
        char* dst = dsm + (size_t)(s ^ 1) * (STAGE_E * 2);
        const bool pf = (c + 1 < nc);
        const float* Anx = A + (size_t)row0 * lda + (size_t)(c + 1) * KC;
        const float* Bnx = B + (size_t)col0 * ldb + (size_t)(c + 1) * KC;

        float4 ra[8];
        if (pf) {
            #pragma unroll
            for (int it = 0; it < 8; it++) {
                int r = lr0 + it * 16;
                ra[it] = *(const float4*)(Anx + (size_t)r * lda + lcg);
            }
        }

        // ---- ksteps 0..1 ----
        #pragma unroll
        for (int ks = 0; ks < 2; ks++) {
            const int k0 = ks * 16;
            uint32_t ah[2][4], al[2][4];
            #pragma unroll
            for (int mt = 0; mt < 2; mt++) {
                uint32_t off = ((32 * wr + 16 * mt + ro) * SKB + k0 + co) * 2;
                ldsm4(ah[mt], sOff + AH_O * 2 + off);
                ldsm4(al[mt], sOff + AL_O * 2 + off);
            }
            uint32_t bh[8][2], bl[8][2];
            #pragma unroll
            for (int p = 0; p < 4; p++) {
                uint32_t off = ((64 * wc + 16 * p + ro) * SKB + k0 + co) * 2;
                uint32_t r[4];
                ldsm4(r, sOff + BH_O * 2 + off);
                bh[2*p][0] = r[0]; bh[2*p][1] = r[2];
                bh[2*p+1][0] = r[1]; bh[2*p+1][1] = r[3];
                ldsm4(r, sOff + BL_O * 2 + off);
                bl[2*p][0] = r[0]; bl[2*p][1] = r[2];
                bl[2*p+1][0] = r[1]; bl[2*p+1][1] = r[3];
            }
            #pragma unroll
            for (int mt = 0; mt < 2; mt++)
                #pragma unroll
                for (int nt = 0; nt < 8; nt++) {
                    mma16816(acc[mt][nt], ah[mt], bh[nt]);
                    mma16816(acc[mt][nt], al[mt], bh[nt]);
                    mma16816(acc[mt][nt], ah[mt], bl[nt]);
                }
        }

        if (pf) {
            #pragma unroll
            for (int it = 0; it < 8; it++) {
                int r = lr0 + it * 16;
                uint2 Hh, Ll;
                split4(ra[it], Hh, Ll);
                *(uint2*)(dst + (AH_O + r * SKB + lcg) * 2) = Hh;
                *(uint2*)(dst + (AL_O + r * SKB + lcg) * 2) = Ll;
            }
            #pragma unroll
            for (int it = 0; it < 8; it++) {
                int r = lr0 + it * 16;
                ra[it] = *(const float4*)(Bnx + (size_t)r * ldb + lcg);
            }
        }

        // ---- ksteps 2..3 ----
        #pragma unroll
        for (int ks = 2; ks < 4; ks++) {
            const int k0 = ks * 16;
            uint32_t ah[2][4], al[2][4];
            #pragma unroll
            for (int mt = 0; mt < 2; mt++) {
                uint32_t off = ((32 * wr + 16 * mt + ro) * SKB + k0 + co) * 2;
                ldsm4(ah[mt], sOff + AH_O * 2 + off);
                ldsm4(al[mt], sOff + AL_O * 2 + off);
            }
            uint32_t bh[8][2], bl[8][2];
            #pragma unroll
            for (int p = 0; p < 4; p++) {
                uint32_t off = ((64 * wc + 16 * p + ro) * SKB + k0 + co) * 2;
                uint32_t r[4];
                ldsm4(r, sOff + BH_O * 2 + off);
                bh[2*p][0] = r[0]; bh[2*p][1] = r[2];
                bh[2*p+1][0] = r[1]; bh[2*p+1][1] = r[3];
                ldsm4(r, sOff + BL_O * 2 + off);
                bl[2*p][0] = r[0]; bl[2*p][1] = r[2];
                bl[2*p+1][0] = r[1]; bl[2*p+1][1] = r[3];
            }
            #pragma unroll
            for (int mt = 0; mt < 2; mt++)
                #pragma unroll
                for (int nt = 0; nt < 8; nt++) {
                    mma16816(acc[mt][nt], ah[mt], bh[nt]);
                    mma16816(acc[mt][nt], al[mt], bh[nt]);
                    mma16816(acc[mt][nt], ah[mt], bl[nt]);
                }
        }

        if (pf) {
            #pragma unroll
            for (int it = 0; it < 8; it++) {
                int r = lr0 + it * 16;
                uint2 Hh, Ll;
                split4(ra[it], Hh, Ll);
                *(uint2*)(dst + (BH_O + r * SKB + lcg) * 2) = Hh;
                *(uint2*)(dst + (BL_O + r * SKB + lcg) * 2) = Ll;
            }
        }
        __syncthreads();
    }

    // ---- epilogue ----
    #pragma unroll
    for (int mt = 0; mt < 2; mt++) {
        #pragma unroll
        for (int nt = 0; nt < 8; nt++) {
            const int r0 = row0 + 32 * wr + 16 * mt + (lane >> 2);
            const int cc = col0 + 64 * wc + 8 * nt + 2 * (lane & 3);
            float2 bv = make_float2(0.f, 0.f);
            if (HB) bv = *(const float2*)&bias[cc];
            #pragma unroll
            for (int hh = 0; hh < 2; hh++) {
                const int r = r0 + hh * 8;
                float v0 = acc[mt][nt][2*hh]     * scale;
                float v1 = acc[mt][nt][2*hh + 1] * scale;
                if (HB) { v0 += bv.x; v1 += bv.y; }
                if (HR) {
                    float2 rv = *(const float2*)&resid[(size_t)r * ldc + cc];
                    v0 += rv.x; v1 += rv.y;
                }
                if (ACT == 1) { v0 = gelu_exact(v0); v1 = gelu_exact(v1); }
                *(float2*)&C[(size_t)r * ldc + cc] = make_float2(v0, v1);
            }
        }
    }
}

// ---------------- V transpose: vt[bh][d][q] = qkv[b,q, 2D + h*HD + d] ----------------
__global__ __launch_bounds__(256) void transpose_v(const float* __restrict__ qkv,
                                                   float* __restrict__ vt)
{
    __shared__ float t[32][33];
    const int bh = blockIdx.z, b = bh / Hc, h = bh % Hc;
    const int q0 = blockIdx.x * 32, d0 = blockIdx.y * 32;
    const int tx = threadIdx.x & 31, ty = threadIdx.x >> 5;   // 32 x 8
    const float* src = qkv + (size_t)b * Lc * D3c + 2 * Dc + h * HDc;
    #pragma unroll
    for (int i = ty; i < 32; i += 8)
        t[i][tx] = src[(size_t)(q0 + i) * D3c + d0 + tx];
    __syncthreads();
    float* dst = vt + (size_t)bh * HDc * Lc;
    #pragma unroll
    for (int i = ty; i < 32; i += 8)
        dst[(size_t)(d0 + i) * Lc + q0 + tx] = t[tx][i];
}

// ---------------- layernorm ----------------
__global__ __launch_bounds__(256)
void layernorm_kernel(const float* __restrict__ x, const float* __restrict__ g,
                      const float* __restrict__ b, float* __restrict__ out)
{
    const int row = blockIdx.x;
    const int t   = threadIdx.x;
    const float4 v = ((const float4*)(x + (size_t)row * Dc))[t];

    float s1 = v.x + v.y + v.z + v.w;
    float s2 = v.x*v.x + v.y*v.y + v.z*v.z + v.w*v.w;

    __shared__ float sh1[8], sh2[8];
    #pragma unroll
    for (int o = 16; o > 0; o >>= 1) {
        s1 += __shfl_down_sync(0xffffffffu, s1, o);
        s2 += __shfl_down_sync(0xffffffffu, s2, o);
    }
    if ((t & 31) == 0) { sh1[t >> 5] = s1; sh2[t >> 5] = s2; }
    __syncthreads();
    if (t < 8) {
        s1 = sh1[t]; s2 = sh2[t];
        #pragma unroll
        for (int o = 4; o > 0; o >>= 1) {
            s1 += __shfl_down_sync(0xffu, s1, o);
            s2 += __shfl_down_sync(0xffu, s2, o);
        }
        if (t == 0) { sh1[0] = s1; sh2[0] = s2; }
    }
    __syncthreads();

    const float mean = sh1[0] * (1.0f / Dc);
    const float var  = sh2[0] * (1.0f / Dc) - mean * mean;
    const float rstd = rsqrtf(var + 1e-5f);

    const float4 gv = ((const float4*)g)[t];
    const float4 bv = ((const float4*)b)[t];
    float4 r;
    r.x = (v.x - mean) * rstd * gv.x + bv.x;
    r.y = (v.y - mean) * rstd * gv.y + bv.y;
    r.z = (v.z - mean) * rstd * gv.z + bv.z;
    r.w = (v.w - mean) * rstd * gv.w + bv.w;
    ((float4*)(out + (size_t)row * Dc))[t] = r;
}

// ---------------- softmax over rows of length L ----------------
__global__ __launch_bounds__(256)
void softmax_kernel(float* __restrict__ s)
{
    const size_t row = blockIdx.x;
    float4* p = (float4*)(s + row * (size_t)Lc);
    const int t = threadIdx.x;

    float4 a = p[t];
    float4 c = p[t + 256];

    float mx = fmaxf(fmaxf(fmaxf(a.x, a.y), fmaxf(a.z, a.w)),
                     fmaxf(fmaxf(c.x, c.y), fmaxf(c.z, c.w)));

    __shared__ float sh[8];
    #pragma unroll
    for (int o = 16; o > 0; o >>= 1) mx = fmaxf(mx, __shfl_down_sync(0xffffffffu, mx, o));
    if ((t & 31) == 0) sh[t >> 5] = mx;
    __syncthreads();
    if (t < 8) {
        mx = sh[t];
        #pragma unroll
        for (int o = 4; o > 0; o >>= 1) mx = fmaxf(mx, __shfl_down_sync(0xffu, mx, o));
        if (t == 0) sh[0] = mx;
    }
    __syncthreads();
    mx = sh[0];
    __syncthreads();

    a.x = expf(a.x - mx); a.y = expf(a.y - mx); a.z = expf(a.z - mx); a.w = expf(a.w - mx);
    c.x = expf(c.x - mx); c.y = expf(c.y - mx); c.z = expf(c.z - mx); c.w = expf(c.w - mx);

    float sm = a.x + a.y + a.z + a.w + c.x + c.y + c.z + c.w;
    #pragma unroll
    for (int o = 16; o > 0; o >>= 1) sm += __shfl_down_sync(0xffffffffu, sm, o);
    if ((t & 31) == 0) sh[t >> 5] = sm;
    __syncthreads();
    if (t < 8) {
        sm = sh[t];
        #pragma unroll
        for (int o = 4; o > 0; o >>= 1) sm += __shfl_down_sync(0xffu, sm, o);
        if (t == 0) sh[0] = sm;
    }
    __syncthreads();
    const float inv = 1.0f / sh[0];

    a.x *= inv; a.y *= inv; a.z *= inv; a.w *= inv;
    c.x *= inv; c.y *= inv; c.z *= inv; c.w *= inv;
    p[t]       = a;
    p[t + 256] = c;
}

// ---------------- host side ----------------
extern "C" void kernel_launch(void* const* d_in, const int* in_sizes, int n_in,
                              void* d_out, int out_size)
{
    const float* x    = (const float*)d_in[0];
    const float* w3d  = (const float*)d_in[1];
    const float* b3d  = (const float*)d_in[2];
    const float* ln1g = (const float*)d_in[3];
    const float* ln1b = (const float*)d_in[4];
    const float* wqkv = (const float*)d_in[5];
    const float* bqkv = (const float*)d_in[6];
    const float* wprj = (const float*)d_in[7];
    const float* bprj = (const float*)d_in[8];
    const float* ln2g = (const float*)d_in[9];
    const float* ln2b = (const float*)d_in[10];
    const float* w1   = (const float*)d_in[11];
    const float* b1   = (const float*)d_in[12];
    const float* w2   = (const float*)d_in[13];
    const float* b2   = (const float*)d_in[14];
    const float* lnfg = (const float*)d_in[15];
    const float* lnfb = (const float*)d_in[16];
    float* out = (float*)d_out;

    float *h, *hn, *qkv, *sc, *o, *f, *vt;
    cudaGetSymbolAddress((void**)&h,   g_h);
    cudaGetSymbolAddress((void**)&hn,  g_hn);
    cudaGetSymbolAddress((void**)&qkv, g_qkv);
    cudaGetSymbolAddress((void**)&sc,  g_sc);
    cudaGetSymbolAddress((void**)&o,   g_o);
    cudaGetSymbolAddress((void**)&f,   g_f);
    cudaGetSymbolAddress((void**)&vt,  g_vt);

    cudaFuncSetAttribute(tc_gemm<true,false,0>,  cudaFuncAttributeMaxDynamicSharedMemorySize, SMEM_DYN);
    cudaFuncSetAttribute(tc_gemm<false,false,0>, cudaFuncAttributeMaxDynamicSharedMemorySize, SMEM_DYN);
    cudaFuncSetAttribute(tc_gemm<true,true,0>,   cudaFuncAttributeMaxDynamicSharedMemorySize, SMEM_DYN);
    cudaFuncSetAttribute(tc_gemm<true,false,1>,  cudaFuncAttributeMaxDynamicSharedMemorySize, SMEM_DYN);

    const dim3 blk(256);

    // ---- embed: h = x @ w3d^T + b3d ----
    tc_gemm<true,false,0><<<dim3(Dc/128, Mc/128, 1), blk, SMEM_DYN>>>(
        x, D3c, w3d, D3c, b3d, nullptr, h, Dc, D3c, 1.0f, 0,0,0,0,0,0, 1);

    for (int i = 0; i < NLc; i++) {
        layernorm_kernel<<<Mc, blk>>>(h, ln1g + (size_t)i*Dc, ln1b + (size_t)i*Dc, hn);

        // qkv = hn @ wqkv^T + bqkv
        tc_gemm<true,false,0><<<dim3(D3c/128, Mc/128, 1), blk, SMEM_DYN>>>(
            hn, Dc, wqkv + (size_t)i*D3c*Dc, Dc, bqkv + (size_t)i*D3c, nullptr,
            qkv, D3c, Dc, 1.0f, 0,0,0,0,0,0, 1);

        // Vt for the PV GEMM
        transpose_v<<<dim3(Lc/32, HDc/32, Bc*Hc), blk>>>(qkv, vt);

        // scores = scale * Q @ K^T  (batched over b,h)
        tc_gemm<false,false,0><<<dim3(Lc/128, Lc/128, Bc*Hc), blk, SMEM_DYN>>>(
            qkv,      D3c,
            qkv + Dc, D3c,
            nullptr, nullptr,
            sc, Lc, HDc, 0.0625f,
            (long)Lc*D3c, (long)HDc,
            (long)Lc*D3c, (long)HDc,
            (long)Hc*Lc*Lc, (long)Lc*Lc,
            Hc);

        softmax_kernel<<<Bc*Hc*Lc, blk>>>(sc);

        // o = P @ V == P @ Vt^T (NT, batched)
        tc_gemm<false,false,0><<<dim3(HDc/128, Lc/128, Bc*Hc), blk, SMEM_DYN>>>(
            sc, Lc,
            vt, Lc,
            nullptr, nullptr,
            o, Dc, Lc, 1.0f,
            (long)Hc*Lc*Lc, (long)Lc*Lc,
            (long)Hc*HDc*Lc, (long)HDc*Lc,
            (long)Lc*Dc, (long)HDc,
            Hc);

        // h = h + o @ wproj^T + bproj
        tc_gemm<true,true,0><<<dim3(Dc/128, Mc/128, 1), blk, SMEM_DYN>>>(
            o, Dc, wprj + (size_t)i*Dc*Dc, Dc, bprj + (size_t)i*Dc, h,
            h, Dc, Dc, 1.0f, 0,0,0,0,0,0, 1);

        layernorm_kernel<<<Mc, blk>>>(h, ln2g + (size_t)i*Dc, ln2b + (size_t)i*Dc, hn);

        // f = gelu(hn @ w1^T + b1)
        tc_gemm<true,false,1><<<dim3(FFc/128, Mc/128, 1), blk, SMEM_DYN>>>(
            hn, Dc, w1 + (size_t)i*FFc*Dc, Dc, b1 + (size_t)i*FFc, nullptr,
            f, FFc, Dc, 1.0f, 0,0,0,0,0,0, 1);

        // h = h + f @ w2^T + b2
        tc_gemm<true,true,0><<<dim3(Dc/128, Mc/128, 1), blk, SMEM_DYN>>>(
            f, FFc, w2 + (size_t)i*Dc*FFc, FFc, b2 + (size_t)i*Dc, h,
            h, Dc, FFc, 1.0f, 0,0,0,0,0,0, 1);
    }

    layernorm_kernel<<<Mc, blk>>>(h, lnfg, lnfb, out);
}